// round 2
// baseline (speedup 1.0000x reference)
#include <cuda_runtime.h>
#include <cuda_bf16.h>
#include <cstdint>

// Shapes (compile-time; all powers of two):
// L=2, B=4, H=8, M=4096, D=128
// k_caches, v_caches : (L,B,H,M,D) f32
// latest_k, latest_v : (L,B,H,1,D) f32
// position_ids       : (B,1) int32
// seq_len            : scalar int (device)
// out                : (2,L,B,H,M,D) f32  = stack([k_out, v_out])
//
// out = stack(caches) with row (l,b,h,pos[b]) replaced by latest when pos[b] < seq_len.
//
// Strategy: pure streaming copy at 64 B/thread (4x float4, front-batched loads
// => MLP_p1=4), streaming cache hints (zero reuse, 268MB >> L2). The 4 float4s
// of one thread always sit inside a single D-row (64 | 512), so the scatter
// predicate is evaluated once per thread.

#define D4_SHIFT  5      // 32 float4 per D-row
#define D4_MASK   31
#define M_SHIFT   12     // M = 4096
#define M_MASK    4095
#define H_SHIFT   3      // H = 8
#define B_MASK    3

#define N4_HALF   (1u << 23)   // float4s per cache tensor (2^25 floats / 4)
#define V4PT      4            // float4s per thread

__global__ __launch_bounds__(256)
void kv_update_kernel(const float4* __restrict__ kc,
                      const float4* __restrict__ vc,
                      const float4* __restrict__ lk,
                      const float4* __restrict__ lv,
                      const int*    __restrict__ pos,     // (B,1)
                      const int*    __restrict__ seq_len, // scalar
                      float4*       __restrict__ out)
{
    const unsigned t  = blockIdx.x * blockDim.x + threadIdx.x;
    const unsigned i0 = t * V4PT;                      // first float4 idx in out
    const bool isV = (i0 >= N4_HALF);
    const unsigned j0 = isV ? (i0 - N4_HALF) : i0;     // idx within one cache tensor

    // All V4PT float4s share the same (m, b): group of 64B inside one 512B row.
    const unsigned m = (j0 >> D4_SHIFT) & M_MASK;
    const unsigned b = (j0 >> (D4_SHIFT + M_SHIFT + H_SHIFT)) & B_MASK;

    const float4* __restrict__ src = isV ? vc : kc;

    float4 v0, v1, v2, v3;

    if ((int)m == pos[b] && (int)m < *seq_len) {
        // latest index (L,B,H,1,D): strip m
        const unsigned lj0 = ((j0 >> (D4_SHIFT + M_SHIFT)) << D4_SHIFT) | (j0 & D4_MASK);
        const float4* __restrict__ lsrc = isV ? lv : lk;
        v0 = lsrc[lj0 + 0];
        v1 = lsrc[lj0 + 1];
        v2 = lsrc[lj0 + 2];
        v3 = lsrc[lj0 + 3];
    } else {
        // Front-batched independent streaming loads (MLP_p1 = 4).
        v0 = __ldcs(src + j0 + 0);
        v1 = __ldcs(src + j0 + 1);
        v2 = __ldcs(src + j0 + 2);
        v3 = __ldcs(src + j0 + 3);
    }

    __stcs(out + i0 + 0, v0);
    __stcs(out + i0 + 1, v1);
    __stcs(out + i0 + 2, v2);
    __stcs(out + i0 + 3, v3);
}

extern "C" void kernel_launch(void* const* d_in, const int* in_sizes, int n_in,
                              void* d_out, int out_size)
{
    const float4* kc  = (const float4*)d_in[0];
    const float4* vc  = (const float4*)d_in[1];
    const float4* lk  = (const float4*)d_in[2];
    const float4* lv  = (const float4*)d_in[3];
    const int*    pos = (const int*)   d_in[4];
    const int*    sl  = (const int*)   d_in[5];
    float4*       out = (float4*)      d_out;

    // total float4s = 2*N4_HALF = 2^24; threads = 2^24/4 = 2^22; blocks = 2^22/256
    const int threads = 256;
    const int blocks  = (int)((2u * N4_HALF / V4PT) / threads);
    kv_update_kernel<<<blocks, threads>>>(kc, vc, lk, lv, pos, sl, out);
}

// round 3
// speedup vs baseline: 1.0511x; 1.0511x over previous
#include <cuda_runtime.h>
#include <cuda_bf16.h>
#include <cstdint>

// L=2, B=4, H=8, M=4096, D=128
// k_caches, v_caches : (L,B,H,M,D) f32
// latest_k, latest_v : (L,B,H,1,D) f32
// position_ids       : (B,1) int32 ; seq_len : scalar int (device)
// out                : (2,L,B,H,M,D) f32 = stack([k_out, v_out])
//
// out = stack(caches) with row (l,b,h,pos[b]) replaced by latest when pos[b] < seq_len.
//
// R3: R1's fully-coalesced layout (1 float4 per thread per LDG, lane stride 16B)
// + MLP_p1=4 via BLOCK-STRIDED batching: thread t covers i0 + k*blockDim,
// k=0..3. Every LDG.128 is 4-line coalesced; 4 independent loads in flight
// per thread. Scatter predicate per element -> predicated pointer select,
// uniform LDG, no wavefront inflation.

#define D4_SHIFT  5      // 32 float4 per D-row
#define D4_MASK   31
#define M_SHIFT   12     // M = 4096
#define M_MASK    4095
#define H_SHIFT   3      // H = 8
#define B_MASK    3

#define N4_HALF   (1u << 23)   // float4s per one cache tensor
#define V4PT      4            // float4s per thread
#define TPB       256

__global__ __launch_bounds__(TPB)
void kv_update_kernel(const float4* __restrict__ kc,
                      const float4* __restrict__ vc,
                      const float4* __restrict__ lk,
                      const float4* __restrict__ lv,
                      const int*    __restrict__ pos,     // (B,1)
                      const int*    __restrict__ seq_len, // scalar
                      float4*       __restrict__ out)
{
    const unsigned i0 = blockIdx.x * (TPB * V4PT) + threadIdx.x;
    const int S = *seq_len;

    // Compute all 4 source pointers first (independent), then 4 loads
    // front-batched, then 4 stores.
    const float4* p[V4PT];

#pragma unroll
    for (int k = 0; k < V4PT; k++) {
        const unsigned i = i0 + k * TPB;               // float4 idx in out
        const bool isV = (i >= N4_HALF);
        const unsigned j = isV ? (i - N4_HALF) : i;    // idx within one cache tensor

        const unsigned m = (j >> D4_SHIFT) & M_MASK;
        const unsigned b = (j >> (D4_SHIFT + M_SHIFT + H_SHIFT)) & B_MASK;

        if ((int)m == __ldg(pos + b) && (int)m < S) {
            const unsigned lj = ((j >> (D4_SHIFT + M_SHIFT)) << D4_SHIFT) | (j & D4_MASK);
            p[k] = (isV ? lv : lk) + lj;
        } else {
            p[k] = (isV ? vc : kc) + j;
        }
    }

    float4 v[V4PT];
#pragma unroll
    for (int k = 0; k < V4PT; k++) v[k] = *p[k];

#pragma unroll
    for (int k = 0; k < V4PT; k++) out[i0 + k * TPB] = v[k];
}

extern "C" void kernel_launch(void* const* d_in, const int* in_sizes, int n_in,
                              void* d_out, int out_size)
{
    const float4* kc  = (const float4*)d_in[0];
    const float4* vc  = (const float4*)d_in[1];
    const float4* lk  = (const float4*)d_in[2];
    const float4* lv  = (const float4*)d_in[3];
    const int*    pos = (const int*)   d_in[4];
    const int*    sl  = (const int*)   d_in[5];
    float4*       out = (float4*)      d_out;

    // total float4s = 2^24 ; per block = TPB*V4PT = 1024 ; blocks = 16384
    const int blocks = (int)((2u * N4_HALF) / (TPB * V4PT));
    kv_update_kernel<<<blocks, TPB>>>(kc, vc, lk, lv, pos, sl, out);
}